// round 4
// baseline (speedup 1.0000x reference)
#include <cuda_runtime.h>

// ---------------------------------------------------------------------------
// PatchTokenizer: hierarchical mask selection + compacted patch gathers.
// Output layout (all float32, tuple order of the reference):
//   [0]  resized0 : 32768 x 768      @ 0
//   [1]  resized1 :  8192 x 768      @ OFF1
//   [2]  resized2 :  2048 x 768      @ OFF2
//   [3]  fulls0   :  8192 x 4 x 768  @ OFF3
//   [4]  fulls1   :  2048 x 16 x 768 @ OFF4
//   [5-7] masks @ OFF5/6/7, [8] counts @ OFF8, [9] output_mask @ OFF9,
//   [10] seqlens, [11] cu_seqlens, [12] max, [13] retained_frac
// ---------------------------------------------------------------------------

#define OFF1 25165824
#define OFF2 31457280
#define OFF3 33030144
#define OFF4 58195968
#define OFF5 83361792
#define OFF6 83394560
#define OFF7 83402752
#define OFF8 83404800
#define OFF9 83404803
#define OFF10 83447843
#define OFF11 83447875
#define OFF12 83447908
#define OFF13 83447909

// scratch (allocation-free rule: __device__ globals)
__device__ unsigned short g_lsel0[32768], g_lsel1[8192], g_lsel2[2048];
__device__ int g_sel0[32768], g_sel1[8192], g_sel2[2048];
__device__ int g_cnt[3];
__device__ int g_scu[33], g_sc0[32], g_sc01[32];

__device__ __forceinline__ float4 zero4() { return make_float4(0.f, 0.f, 0.f, 0.f); }

// ---- Fused mask kernel: 1 block, 1024 threads, warp-per-batch -------------
__global__ void __launch_bounds__(1024)
mask_kernel(const float* __restrict__ imp1, const float* __restrict__ imp2,
            float* __restrict__ out) {
    __shared__ unsigned char sm2[2048];   // 32 x 64
    __shared__ unsigned char sm1[8192];   // 32 x 256
    __shared__ unsigned char sm0[32768];  // 32 x 1024
    __shared__ int sCnt0[32], sCnt1[32], sCnt2[32];
    __shared__ int sOff0[32], sOff1[32], sOff2[32];

    const int tid = threadIdx.x;
    const int b = tid >> 5;      // batch = warp
    const int l = tid & 31;      // lane

    // ---- phase 1: masks (warp-private per batch) -------------------------
    unsigned char v2[2];
#pragma unroll
    for (int k = 0; k < 2; k++) {
        int j = l * 2 + k;
        v2[k] = imp2[b * 64 + j] < 0.3f;
        sm2[b * 64 + j] = v2[k];
    }
    __syncwarp();

    unsigned char v1[8];
#pragma unroll
    for (int k = 0; k < 8; k++) {
        int j = l * 8 + k;
        int r = j >> 4, c = j & 15;
        unsigned char cov2 = sm2[b * 64 + ((r >> 1) << 3) + (c >> 1)];
        v1[k] = (imp1[b * 256 + j] < 0.5f) && !cov2;
        sm1[b * 256 + j] = v1[k];
    }
    __syncwarp();

    unsigned char v0[32];
    int c0 = 0;
#pragma unroll
    for (int k = 0; k < 32; k++) {
        int j = l * 32 + k;
        int r = j >> 5, c = j & 31;
        unsigned char cov = sm2[b * 64 + ((r >> 2) << 3) + (c >> 2)] |
                            sm1[b * 256 + ((r >> 1) << 4) + (c >> 1)];
        v0[k] = !cov;
        sm0[b * 1024 + j] = v0[k];
        c0 += v0[k];
    }

    // ---- warp scans -> local compaction lists ----------------------------
    int c1 = v1[0] + v1[1] + v1[2] + v1[3] + v1[4] + v1[5] + v1[6] + v1[7];
    int c2 = v2[0] + v2[1];
    int i0 = c0, i1 = c1, i2 = c2;
#pragma unroll
    for (int o = 1; o < 32; o <<= 1) {
        int n0 = __shfl_up_sync(0xffffffffu, i0, o);
        int n1 = __shfl_up_sync(0xffffffffu, i1, o);
        int n2 = __shfl_up_sync(0xffffffffu, i2, o);
        if (l >= o) { i0 += n0; i1 += n1; i2 += n2; }
    }
    {
        int r = i0 - c0;
#pragma unroll
        for (int k = 0; k < 32; k++)
            if (v0[k]) g_lsel0[b * 1024 + r++] = (unsigned short)(l * 32 + k);
    }
    {
        int r = i1 - c1;
#pragma unroll
        for (int k = 0; k < 8; k++)
            if (v1[k]) g_lsel1[b * 256 + r++] = (unsigned short)(l * 8 + k);
    }
    {
        int r = i2 - c2;
#pragma unroll
        for (int k = 0; k < 2; k++)
            if (v2[k]) g_lsel2[b * 64 + r++] = (unsigned short)(l * 2 + k);
    }
    int t0 = __shfl_sync(0xffffffffu, i0, 31);
    int t1 = __shfl_sync(0xffffffffu, i1, 31);
    int t2 = __shfl_sync(0xffffffffu, i2, 31);
    if (l == 0) {
        sCnt0[b] = t0; sCnt1[b] = t1; sCnt2[b] = t2;
        out[OFF10 + b] = (float)(1 + t0 + t1 + t2);
    }
    __syncthreads();

    // ---- phase 2: cross-batch stitch (warp 0) ----------------------------
    if (tid < 32) {
        int bc0 = sCnt0[tid], bc1 = sCnt1[tid], bc2 = sCnt2[tid];
        int sl = 1 + bc0 + bc1 + bc2;
        int a0 = bc0, a1 = bc1, a2 = bc2, as_ = sl;
#pragma unroll
        for (int o = 1; o < 32; o <<= 1) {
            int n0 = __shfl_up_sync(0xffffffffu, a0, o);
            int n1 = __shfl_up_sync(0xffffffffu, a1, o);
            int n2 = __shfl_up_sync(0xffffffffu, a2, o);
            int ns = __shfl_up_sync(0xffffffffu, as_, o);
            if (tid >= o) { a0 += n0; a1 += n1; a2 += n2; as_ += ns; }
        }
        sOff0[tid] = a0 - bc0;
        sOff1[tid] = a1 - bc1;
        sOff2[tid] = a2 - bc2;
        g_scu[tid + 1] = as_;
        g_sc0[tid] = bc0;
        g_sc01[tid] = bc0 + bc1;
        out[OFF11 + 1 + tid] = (float)as_;
        int mx = sl;
#pragma unroll
        for (int o = 16; o; o >>= 1) {
            int n = __shfl_xor_sync(0xffffffffu, mx, o);
            mx = mx > n ? mx : n;
        }
        if (tid == 0) {
            g_scu[0] = 0;
            out[OFF11] = 0.0f;
            out[OFF12] = (float)mx;
        }
        if (tid == 31) {
            g_cnt[0] = a0; g_cnt[1] = a1; g_cnt[2] = a2;
            out[OFF8 + 0] = (float)a0;
            out[OFF8 + 1] = (float)a1;
            out[OFF8 + 2] = (float)a2;
            out[OFF13] = (float)as_ / 32768.0f;
        }
    }
    __syncthreads();

    // ---- phase 3: coalesced mask-float outputs + global sel arrays -------
    {
        const uchar4* s0 = reinterpret_cast<const uchar4*>(sm0);
        float4* d0 = reinterpret_cast<float4*>(out + OFF5);
        for (int i = tid; i < 8192; i += 1024) {
            uchar4 u = s0[i];
            d0[i] = make_float4((float)u.x, (float)u.y, (float)u.z, (float)u.w);
        }
        const uchar4* s1 = reinterpret_cast<const uchar4*>(sm1);
        float4* d1 = reinterpret_cast<float4*>(out + OFF6);
        for (int i = tid; i < 2048; i += 1024) {
            uchar4 u = s1[i];
            d1[i] = make_float4((float)u.x, (float)u.y, (float)u.z, (float)u.w);
        }
        const uchar4* s2 = reinterpret_cast<const uchar4*>(sm2);
        float4* d2 = reinterpret_cast<float4*>(out + OFF7);
        if (tid < 512) {
            uchar4 u = s2[tid];
            d2[tid] = make_float4((float)u.x, (float)u.y, (float)u.z, (float)u.w);
        }
    }
    for (int i = tid; i < 32768; i += 1024) {
        int bb = i >> 10, r = i & 1023;
        if (r < sCnt0[bb]) g_sel0[sOff0[bb] + r] = (int)g_lsel0[i] + (bb << 10);
    }
    for (int i = tid; i < 8192; i += 1024) {
        int bb = i >> 8, r = i & 255;
        if (r < sCnt1[bb]) g_sel1[sOff1[bb] + r] = (int)g_lsel1[i] + (bb << 8);
    }
    for (int i = tid; i < 2048; i += 1024) {
        int bb = i >> 6, r = i & 63;
        if (r < sCnt2[bb]) g_sel2[sOff2[bb] + r] = (int)g_lsel2[i] + (bb << 6);
    }
}

// ---------------------------------------------------------------------------
// Mega kernel: five big sections + output_mask section, block ranges:
// ---------------------------------------------------------------------------
#define NB0 3072
#define NB1 3072
#define NB2 1536
#define NB3 3072
#define NB4 3072
#define NB5 32
#define E0 (NB0)
#define E1 (NB0 + NB1)
#define E2 (NB0 + NB1 + NB2)
#define E3 (NB0 + NB1 + NB2 + NB3)
#define E4 (NB0 + NB1 + NB2 + NB3 + NB4)
#define NBLK (E4 + NB5)

__global__ void __launch_bounds__(256)
mega_kernel(const float* __restrict__ img, float* __restrict__ out) {
    const int bs = blockIdx.x;
    const int tid = threadIdx.x;

    if (bs < E0) {
        // ---- S0: resized0 (pure copy of 16x16 base patches) --------------
        const int cnt = g_cnt[0];
        const int base = bs * 2048 + tid;
        const float* src[8];
#pragma unroll
        for (int k = 0; k < 8; k++) {
            int i = base + k * 256;
            int p = i / 192, t4 = i - p * 192;
            if (p < cnt) {
                int s = g_sel0[p];
                int b = s >> 10, gy = (s >> 5) & 31, gx = s & 31;
                int e = t4 << 2;
                int c = e >> 8, y = (e >> 4) & 15, x = e & 15;
                src[k] = img + ((b * 3 + c) * 512 + gy * 16 + y) * 512 + gx * 16 + x;
            } else src[k] = nullptr;
        }
        float4 v[8];
#pragma unroll
        for (int k = 0; k < 8; k++)
            v[k] = src[k] ? *reinterpret_cast<const float4*>(src[k]) : zero4();
        float4* dst = reinterpret_cast<float4*>(out);
#pragma unroll
        for (int k = 0; k < 8; k++) dst[base + k * 256] = v[k];

    } else if (bs < E1) {
        // ---- S1: resized1 (2x2 average of original) -----------------------
        const int cnt = g_cnt[1];
        const int base = (bs - E0) * 512 + tid;
        const float* bp[2];
#pragma unroll
        for (int k = 0; k < 2; k++) {
            int i = base + k * 256;
            int p = i / 192, t4 = i - p * 192;
            if (p < cnt) {
                int s = g_sel1[p];
                int b = s >> 8, gy = (s >> 4) & 15, gx = s & 15;
                int e = t4 << 2;
                int c = e >> 8, y = (e >> 4) & 15, x = e & 15;
                int R = gy * 32 + 2 * y, Cc = gx * 32 + 2 * x;
                bp[k] = img + ((b * 3 + c) * 512 + R) * 512 + Cc;
            } else bp[k] = nullptr;
        }
        float4 a0[2], a1[2], b0[2], b1[2];
#pragma unroll
        for (int k = 0; k < 2; k++) {
            if (bp[k]) {
                a0[k] = *(const float4*)(bp[k]);
                a1[k] = *(const float4*)(bp[k] + 4);
                b0[k] = *(const float4*)(bp[k] + 512);
                b1[k] = *(const float4*)(bp[k] + 516);
            }
        }
        float4* dst = reinterpret_cast<float4*>(out + OFF1);
#pragma unroll
        for (int k = 0; k < 2; k++) {
            float4 o = zero4();
            if (bp[k]) {
                o.x = (a0[k].x + a0[k].y + b0[k].x + b0[k].y) * 0.25f;
                o.y = (a0[k].z + a0[k].w + b0[k].z + b0[k].w) * 0.25f;
                o.z = (a1[k].x + a1[k].y + b1[k].x + b1[k].y) * 0.25f;
                o.w = (a1[k].z + a1[k].w + b1[k].z + b1[k].w) * 0.25f;
            }
            dst[base + k * 256] = o;
        }

    } else if (bs < E2) {
        // ---- S2: resized2 (central 2x2 average, 4x downsample) ------------
        const int cnt = g_cnt[2];
        const int i = (bs - E1) * 256 + tid;
        const int p = i / 192, t4 = i - p * 192;
        float4 o = zero4();
        if (p < cnt) {
            int s = g_sel2[p];
            int b = s >> 6, gy = (s >> 3) & 7, gx = s & 7;
            int e = t4 << 2;
            int c = e >> 8, y = (e >> 4) & 15, x = e & 15;
            int R0 = gy * 64 + 4 * y + 1;
            int Cb = gx * 64 + 4 * x;
            const float* r0 = img + ((b * 3 + c) * 512 + R0) * 512 + Cb;
            const float* r1 = r0 + 512;
            float4 q0 = *(const float4*)r0, q1 = *(const float4*)(r0 + 4);
            float4 q2 = *(const float4*)(r0 + 8), q3 = *(const float4*)(r0 + 12);
            float4 u0 = *(const float4*)r1, u1 = *(const float4*)(r1 + 4);
            float4 u2 = *(const float4*)(r1 + 8), u3 = *(const float4*)(r1 + 12);
            o.x = (q0.y + q0.z + u0.y + u0.z) * 0.25f;
            o.y = (q1.y + q1.z + u1.y + u1.z) * 0.25f;
            o.z = (q2.y + q2.z + u2.y + u2.z) * 0.25f;
            o.w = (q3.y + q3.z + u3.y + u3.z) * 0.25f;
        }
        reinterpret_cast<float4*>(out + OFF2)[i] = o;

    } else if (bs < E3) {
        // ---- S3: fulls0 (2x2 constituent base patches, pure copy) ---------
        const int cnt = g_cnt[1];
        const int base = (bs - E2) * 2048 + tid;
        const float* src[8];
#pragma unroll
        for (int k = 0; k < 8; k++) {
            int i = base + k * 256;
            int p = i / 768, rf = i - p * 768;
            if (p < cnt) {
                int s = g_sel1[p];
                int b = s >> 8, gy = (s >> 4) & 15, gx = s & 15;
                int e = rf << 2;
                int sub = e / 768, rem = e - sub * 768;
                int c = rem >> 8, y = (rem >> 4) & 15, x = rem & 15;
                int ny = sub >> 1, nx = sub & 1;
                int R = gy * 32 + ny * 16 + y, Cc = gx * 32 + nx * 16 + x;
                src[k] = img + ((b * 3 + c) * 512 + R) * 512 + Cc;
            } else src[k] = nullptr;
        }
        float4 v[8];
#pragma unroll
        for (int k = 0; k < 8; k++)
            v[k] = src[k] ? *reinterpret_cast<const float4*>(src[k]) : zero4();
        float4* dst = reinterpret_cast<float4*>(out + OFF3);
#pragma unroll
        for (int k = 0; k < 8; k++) dst[base + k * 256] = v[k];

    } else if (bs < E4) {
        // ---- S4: fulls1 (4x4 constituent base patches, pure copy) ---------
        const int cnt = g_cnt[2];
        const int base = (bs - E3) * 2048 + tid;
        const float* src[8];
#pragma unroll
        for (int k = 0; k < 8; k++) {
            int i = base + k * 256;
            int p = i / 3072, rf = i - p * 3072;
            if (p < cnt) {
                int s = g_sel2[p];
                int b = s >> 6, gy = (s >> 3) & 7, gx = s & 7;
                int e = rf << 2;
                int sub = e / 768, rem = e - sub * 768;
                int c = rem >> 8, y = (rem >> 4) & 15, x = rem & 15;
                int ny = sub >> 2, nx = sub & 3;
                int R = gy * 64 + ny * 16 + y, Cc = gx * 64 + nx * 16 + x;
                src[k] = img + ((b * 3 + c) * 512 + R) * 512 + Cc;
            } else src[k] = nullptr;
        }
        float4 v[8];
#pragma unroll
        for (int k = 0; k < 8; k++)
            v[k] = src[k] ? *reinterpret_cast<const float4*>(src[k]) : zero4();
        float4* dst = reinterpret_cast<float4*>(out + OFF4);
#pragma unroll
        for (int k = 0; k < 8; k++) dst[base + k * 256] = v[k];

    } else {
        // ---- S5: compacted output_mask (dest-driven) ----------------------
        const int rel = bs - E4;
        const int tot = g_scu[32];
        for (int j = rel * 256 + tid; j < 43040; j += NB5 * 256) {
            float v = 0.0f;
            if (j < tot) {
                int b = 0;
                while (g_scu[b + 1] <= j) b++;
                int r = j - g_scu[b];
                if (r == 0) v = -1.0f;
                else {
                    r -= 1;
                    if (r < g_sc0[b]) v = 1.0f;
                    else if (r < g_sc01[b]) v = 2.0f;
                    else v = 3.0f;
                }
            }
            out[OFF9 + j] = v;
        }
    }
}

extern "C" void kernel_launch(void* const* d_in, const int* in_sizes, int n_in,
                              void* d_out, int out_size) {
    const float* img = (const float*)d_in[0];   // images  (32,3,512,512)
    const float* i1  = (const float*)d_in[2];   // imp_s1  (32,16,16)
    const float* i2  = (const float*)d_in[3];   // imp_s2  (32,8,8)
    float* out = (float*)d_out;

    mask_kernel<<<1, 1024>>>(i1, i2, out);
    mega_kernel<<<NBLK, 256>>>(img, out);
}